// round 1
// baseline (speedup 1.0000x reference)
#include <cuda_runtime.h>
#include <cuda_bf16.h>
#include <cstdint>

#define DIM 1024
#define NH 16
#define HD 64
#define BT 4096            // B*T tokens
#define TSEQ 2048
#define GROUP 128

// ---------------- scratch (device globals; no allocation allowed) ----------------
__device__ float g_qw[4 * DIM * DIM];    // quantized weights: q,k,v,o
__device__ float g_xq[BT * DIM];         // quantized activations (reused)
__device__ float g_q [BT * DIM];
__device__ float g_k [BT * DIM];
__device__ float g_v [BT * DIM];
__device__ float g_ao[BT * DIM];         // attention output

// ---------------- weight quantization: per-(row,group) ternary -------------------
// block = one (matrix,row,group); 128 threads, one element each
__global__ void quant_w_kernel(const float* __restrict__ w0, const float* __restrict__ w1,
                               const float* __restrict__ w2, const float* __restrict__ w3) {
    int blk = blockIdx.x;
    int g   = blk & 7;
    int row = (blk >> 3) & (DIM - 1);
    int m   = blk >> 13;                       // /(8*1024)
    const float* w = (m == 0) ? w0 : (m == 1) ? w1 : (m == 2) ? w2 : w3;
    int base = row * DIM + g * GROUP;
    float v = w[base + threadIdx.x];
    float a = fabsf(v);
    #pragma unroll
    for (int o = 16; o; o >>= 1) a += __shfl_xor_sync(0xffffffffu, a, o);
    __shared__ float sh[4];
    if ((threadIdx.x & 31) == 0) sh[threadIdx.x >> 5] = a;
    __syncthreads();
    float ws = (sh[0] + sh[1] + sh[2] + sh[3]) * (1.0f / GROUP) + 1e-5f;
    float q = fminf(fmaxf(rintf(v / ws), -1.f), 1.f) * ws;
    g_qw[m * (DIM * DIM) + base + threadIdx.x] = q;
}

// ---------------- activation quantization: per-token absmax ----------------------
__global__ void quant_x_kernel(const float* __restrict__ x, float* __restrict__ xq) {
    int tkn = blockIdx.x;                       // 0..4095
    const float* xr = x + (size_t)tkn * DIM;
    float mx = 0.f;
    for (int i = threadIdx.x; i < DIM; i += 256) mx = fmaxf(mx, fabsf(xr[i]));
    #pragma unroll
    for (int o = 16; o; o >>= 1) mx = fmaxf(mx, __shfl_xor_sync(0xffffffffu, mx, o));
    __shared__ float sh[8];
    if ((threadIdx.x & 31) == 0) sh[threadIdx.x >> 5] = mx;
    __syncthreads();
    float m = sh[0];
    #pragma unroll
    for (int i = 1; i < 8; i++) m = fmaxf(m, sh[i]);
    float s = 127.f / (m + 1e-5f);
    for (int i = threadIdx.x; i < DIM; i += 256) {
        float v = xr[i];
        xq[(size_t)tkn * DIM + i] = fminf(fmaxf(rintf(v * s), -128.f), 127.f) / s;
    }
}

// ---------------- SGEMM: C[M,N] = A[M,K] * W[N,K]^T (both row-major) -------------
#define BM 128
#define BN 128
#define BKK 8
__global__ __launch_bounds__(256, 2)
void gemm_kernel(const float* __restrict__ A, const float* __restrict__ W,
                 float* __restrict__ C, int M, int N, int K) {
    __shared__ float As[BKK][BM];
    __shared__ float Bs[BKK][BN];
    int t = threadIdx.x;
    int rowBlk = blockIdx.y * BM;
    int colBlk = blockIdx.x * BN;
    int tr = t >> 4, tc = t & 15;               // 16x16 thread grid, 8x8 each
    int loadRow = t >> 1;
    int loadK4  = (t & 1) * 4;
    float acc[8][8];
    #pragma unroll
    for (int i = 0; i < 8; i++)
        #pragma unroll
        for (int j = 0; j < 8; j++) acc[i][j] = 0.f;

    for (int k0 = 0; k0 < K; k0 += BKK) {
        float4 av = *(const float4*)&A[(size_t)(rowBlk + loadRow) * K + k0 + loadK4];
        float4 bv = *(const float4*)&W[(size_t)(colBlk + loadRow) * K + k0 + loadK4];
        As[loadK4 + 0][loadRow] = av.x; As[loadK4 + 1][loadRow] = av.y;
        As[loadK4 + 2][loadRow] = av.z; As[loadK4 + 3][loadRow] = av.w;
        Bs[loadK4 + 0][loadRow] = bv.x; Bs[loadK4 + 1][loadRow] = bv.y;
        Bs[loadK4 + 2][loadRow] = bv.z; Bs[loadK4 + 3][loadRow] = bv.w;
        __syncthreads();
        #pragma unroll
        for (int kk = 0; kk < BKK; kk++) {
            float a[8], b[8];
            *(float4*)&a[0] = *(const float4*)&As[kk][tr * 8];
            *(float4*)&a[4] = *(const float4*)&As[kk][tr * 8 + 4];
            *(float4*)&b[0] = *(const float4*)&Bs[kk][tc * 8];
            *(float4*)&b[4] = *(const float4*)&Bs[kk][tc * 8 + 4];
            #pragma unroll
            for (int i = 0; i < 8; i++)
                #pragma unroll
                for (int j = 0; j < 8; j++) acc[i][j] += a[i] * b[j];
        }
        __syncthreads();
    }
    #pragma unroll
    for (int i = 0; i < 8; i++) {
        float* crow = C + (size_t)(rowBlk + tr * 8 + i) * N + colBlk + tc * 8;
        *(float4*)&crow[0] = make_float4(acc[i][0], acc[i][1], acc[i][2], acc[i][3]);
        *(float4*)&crow[4] = make_float4(acc[i][4], acc[i][5], acc[i][6], acc[i][7]);
    }
}

// ---------------- RoPE on q and k (in place) -------------------------------------
__global__ void rope_kernel(float* __restrict__ q, float* __restrict__ k,
                            const float* __restrict__ cs, const float* __restrict__ sn) {
    int idx = blockIdx.x * blockDim.x + threadIdx.x;      // B*T*NH*32 pairs
    if (idx >= 2 * TSEQ * NH * 32) return;
    int d2 = idx & 31;
    int h  = (idx >> 5) & 15;
    int tt = (idx >> 9) & (TSEQ - 1);
    int b  = idx >> 20;
    float c = cs[tt * 32 + d2], s = sn[tt * 32 + d2];
    size_t off = ((size_t)(b * TSEQ + tt)) * DIM + h * HD + d2 * 2;
    {
        float e = q[off], o = q[off + 1];
        q[off] = e * c - o * s; q[off + 1] = e * s + o * c;
    }
    {
        float e = k[off], o = k[off + 1];
        k[off] = e * c - o * s; k[off + 1] = e * s + o * c;
    }
}

// ---------------- flash attention (causal, fp32) ---------------------------------
// grid: (16 qtiles, 32 bh); block: 128 threads, 1 query/thread; KT=64 keys/tile
#define QT 128
#define KT 64
#define SMEM_ATTN ((KT*HD + KT*HD + QT*66) * 4)
__global__ __launch_bounds__(QT)
void attn_kernel(const float* __restrict__ qb, const float* __restrict__ kb,
                 const float* __restrict__ vb, float* __restrict__ ob) {
    extern __shared__ float smem[];
    float* Ks = smem;                 // KT x 64
    float* Vs = Ks + KT * HD;         // KT x 64
    float* Ss = Vs + KT * HD;         // QT x 66 (padded)
    int qtile = blockIdx.x;
    int bh = blockIdx.y;
    int b = bh >> 4, h = bh & 15;
    int tid = threadIdx.x;
    int qi = qtile * QT + tid;

    const float* qrow = qb + ((size_t)(b * TSEQ + qi)) * DIM + h * HD;
    float qreg[HD];
    #pragma unroll
    for (int d = 0; d < HD; d++) qreg[d] = qrow[d];
    float acc[HD];
    #pragma unroll
    for (int d = 0; d < HD; d++) acc[d] = 0.f;
    float m = -1e30f, l = 0.f;
    float* srow = Ss + tid * 66;

    int ntiles = qtile * 2 + 2;
    for (int kt = 0; kt < ntiles; kt++) {
        int jb = kt * KT;
        for (int i = tid; i < KT * HD; i += QT) {
            int r = i >> 6, c2 = i & 63;
            size_t g = ((size_t)(b * TSEQ + jb + r)) * DIM + h * HD + c2;
            Ks[i] = kb[g];
            Vs[i] = vb[g];
        }
        __syncthreads();

        float tmax = -1e30f;
        for (int j = 0; j < KT; j++) {
            const float4* kr4 = (const float4*)(Ks + j * HD);
            float s0 = 0, s1 = 0, s2 = 0, s3 = 0;
            #pragma unroll
            for (int d4 = 0; d4 < 16; d4++) {
                float4 kv = kr4[d4];
                s0 += qreg[4 * d4 + 0] * kv.x;
                s1 += qreg[4 * d4 + 1] * kv.y;
                s2 += qreg[4 * d4 + 2] * kv.z;
                s3 += qreg[4 * d4 + 3] * kv.w;
            }
            float s = ((s0 + s1) + (s2 + s3)) * 0.125f;
            if (jb + j > qi) s = -1e30f;
            srow[j] = s;
            tmax = fmaxf(tmax, s);
        }
        float mnew = fmaxf(m, tmax);
        float corr = __expf(m - mnew);
        m = mnew;
        float sum = 0.f;
        for (int j = 0; j < KT; j++) {
            float p = __expf(srow[j] - m);
            srow[j] = p;
            sum += p;
        }
        l = l * corr + sum;
        #pragma unroll
        for (int d = 0; d < HD; d++) acc[d] *= corr;
        for (int j = 0; j < KT; j++) {
            float p = srow[j];
            const float4* vr4 = (const float4*)(Vs + j * HD);
            #pragma unroll
            for (int d4 = 0; d4 < 16; d4++) {
                float4 vv = vr4[d4];
                acc[4 * d4 + 0] += p * vv.x;
                acc[4 * d4 + 1] += p * vv.y;
                acc[4 * d4 + 2] += p * vv.z;
                acc[4 * d4 + 3] += p * vv.w;
            }
        }
        __syncthreads();
    }
    float invl = 1.f / l;
    float* orow = ob + ((size_t)(b * TSEQ + qi)) * DIM + h * HD;
    #pragma unroll
    for (int d4 = 0; d4 < 16; d4++) {
        *(float4*)&orow[4 * d4] = make_float4(acc[4 * d4 + 0] * invl, acc[4 * d4 + 1] * invl,
                                              acc[4 * d4 + 2] * invl, acc[4 * d4 + 3] * invl);
    }
}

// ---------------- launch ----------------------------------------------------------
extern "C" void kernel_launch(void* const* d_in, const int* in_sizes, int n_in,
                              void* d_out, int out_size) {
    const float* x    = (const float*)d_in[0];
    const float* cosp = (const float*)d_in[1];
    const float* sinp = (const float*)d_in[2];
    const float* wq_w = (const float*)d_in[3];
    const float* wk_w = (const float*)d_in[4];
    const float* wv_w = (const float*)d_in[5];
    const float* wo_w = (const float*)d_in[6];
    float* out = (float*)d_out;

    void* p;
    cudaGetSymbolAddress(&p, g_qw); float* qwp = (float*)p;
    cudaGetSymbolAddress(&p, g_xq); float* xqp = (float*)p;
    cudaGetSymbolAddress(&p, g_q);  float* qp  = (float*)p;
    cudaGetSymbolAddress(&p, g_k);  float* kp  = (float*)p;
    cudaGetSymbolAddress(&p, g_v);  float* vp  = (float*)p;
    cudaGetSymbolAddress(&p, g_ao); float* aop = (float*)p;

    cudaFuncSetAttribute(attn_kernel, cudaFuncAttributeMaxDynamicSharedMemorySize, SMEM_ATTN);

    quant_w_kernel<<<4 * DIM * 8, 128>>>(wq_w, wk_w, wv_w, wo_w);
    quant_x_kernel<<<BT, 256>>>(x, xqp);

    dim3 ggrid(DIM / BN, BT / BM);
    gemm_kernel<<<ggrid, 256>>>(xqp, qwp + 0 * DIM * DIM, qp, BT, DIM, DIM);
    gemm_kernel<<<ggrid, 256>>>(xqp, qwp + 1 * DIM * DIM, kp, BT, DIM, DIM);
    gemm_kernel<<<ggrid, 256>>>(xqp, qwp + 2 * DIM * DIM, vp, BT, DIM, DIM);

    int npairs = 2 * TSEQ * NH * 32;
    rope_kernel<<<(npairs + 255) / 256, 256>>>(qp, kp, cosp, sinp);

    attn_kernel<<<dim3(TSEQ / QT, 2 * NH), QT, SMEM_ATTN>>>(qp, kp, vp, aop);

    quant_x_kernel<<<BT, 256>>>(aop, xqp);
    gemm_kernel<<<ggrid, 256>>>(xqp, qwp + 3 * DIM * DIM, out, BT, DIM, DIM);
}

// round 2
// speedup vs baseline: 1.4446x; 1.4446x over previous
#include <cuda_runtime.h>
#include <cuda_bf16.h>
#include <cstdint>

#define DIM 1024
#define NH 16
#define HD 64
#define BT 4096            // B*T tokens
#define TSEQ 2048
#define GROUP 128

// ---------------- scratch (device globals; no allocation allowed) ----------------
__device__ int8_t g_wi[4 * DIM * DIM];   // ternary weights as int8: q,k,v,o
__device__ float  g_ws[4 * DIM * 8];     // per-(matrix,row,group) scales
__device__ int8_t g_xi[BT * DIM];        // int8 activations (reused)
__device__ float  g_sx[BT];              // per-token 1/s (dequant scale)
__device__ float  g_q [BT * DIM];
__device__ float  g_k [BT * DIM];
__device__ float  g_v [BT * DIM];
__device__ float  g_ao[BT * DIM];        // attention output

// ---------------- weight quantization: per-(row,group) ternary -> int8 -----------
// block = one (matrix,row,group); 128 threads, one element each
__global__ void quant_w_kernel(const float* __restrict__ w0, const float* __restrict__ w1,
                               const float* __restrict__ w2, const float* __restrict__ w3) {
    int blk = blockIdx.x;
    int g   = blk & 7;
    int row = (blk >> 3) & (DIM - 1);
    int m   = blk >> 13;                       // /(8*1024)
    const float* w = (m == 0) ? w0 : (m == 1) ? w1 : (m == 2) ? w2 : w3;
    int base = row * DIM + g * GROUP;
    float v = w[base + threadIdx.x];
    float a = fabsf(v);
    #pragma unroll
    for (int o = 16; o; o >>= 1) a += __shfl_xor_sync(0xffffffffu, a, o);
    __shared__ float sh[4];
    if ((threadIdx.x & 31) == 0) sh[threadIdx.x >> 5] = a;
    __syncthreads();
    float ws = (sh[0] + sh[1] + sh[2] + sh[3]) * (1.0f / GROUP) + 1e-5f;
    float q = fminf(fmaxf(rintf(v / ws), -1.f), 1.f);
    g_wi[m * (DIM * DIM) + base + threadIdx.x] = (int8_t)q;
    if (threadIdx.x == 0) g_ws[(m * DIM + row) * 8 + g] = ws;
}

// ---------------- activation quantization: per-token absmax -> int8 --------------
__global__ void quant_x_kernel(const float* __restrict__ x, int8_t* __restrict__ xi,
                               float* __restrict__ sx) {
    int tkn = blockIdx.x;                       // 0..4095
    const float* xr = x + (size_t)tkn * DIM;
    float mx = 0.f;
    for (int i = threadIdx.x; i < DIM; i += 256) mx = fmaxf(mx, fabsf(xr[i]));
    #pragma unroll
    for (int o = 16; o; o >>= 1) mx = fmaxf(mx, __shfl_xor_sync(0xffffffffu, mx, o));
    __shared__ float sh[8];
    if ((threadIdx.x & 31) == 0) sh[threadIdx.x >> 5] = mx;
    __syncthreads();
    float m = sh[0];
    #pragma unroll
    for (int i = 1; i < 8; i++) m = fmaxf(m, sh[i]);
    float s = 127.f / (m + 1e-5f);
    for (int i = threadIdx.x; i < DIM; i += 256) {
        float v = xr[i];
        xi[(size_t)tkn * DIM + i] = (int8_t)fminf(fmaxf(rintf(v * s), -128.f), 127.f);
    }
    if (threadIdx.x == 0) sx[tkn] = 1.0f / s;
}

// ---------------- int8 dp4a GEMM with per-group scaling ---------------------------
// C[t,o] = sx[t] * sum_g ws[o,g] * ( sum_{i in group g} xi[t,i]*wi[o,i] )
// tile 128x128, K-tile = one group (128), 256 threads, 8x8 per thread
__global__ __launch_bounds__(256, 1)
void gemm_i8_kernel(const int8_t* __restrict__ Xi, const int8_t* __restrict__ Wi,
                    const float* __restrict__ ws, const float* __restrict__ sx,
                    float* __restrict__ C) {
    __shared__ uint32_t As[32][128];     // [kk(=4 bytes of k)][m]
    __shared__ uint32_t Bs[32][128];     // [kk][n]
    __shared__ float    wss[8][128];     // [group][n]
    int t = threadIdx.x;
    int rowBlk = blockIdx.y * 128;
    int colBlk = blockIdx.x * 128;
    int tr = t >> 4, tc = t & 15;

    for (int i = t; i < 8 * 128; i += 256) {
        int col = i & 127, g = i >> 7;
        wss[g][col] = ws[(colBlk + col) * 8 + g];
    }

    float facc[8][8];
    int   iacc[8][8];
    #pragma unroll
    for (int i = 0; i < 8; i++)
        #pragma unroll
        for (int j = 0; j < 8; j++) { facc[i][j] = 0.f; iacc[i][j] = 0; }

    for (int g = 0; g < 8; g++) {
        int k0 = g * GROUP;
        #pragma unroll
        for (int r = 0; r < 4; r++) {
            int u = t + 256 * r;           // 0..1023 uint4 slots
            int row = u >> 3, c = u & 7;
            uint4 av = *(const uint4*)(Xi + (size_t)(rowBlk + row) * DIM + k0 + c * 16);
            uint4 bv = *(const uint4*)(Wi + (size_t)(colBlk + row) * DIM + k0 + c * 16);
            As[c * 4 + 0][row] = av.x; As[c * 4 + 1][row] = av.y;
            As[c * 4 + 2][row] = av.z; As[c * 4 + 3][row] = av.w;
            Bs[c * 4 + 0][row] = bv.x; Bs[c * 4 + 1][row] = bv.y;
            Bs[c * 4 + 2][row] = bv.z; Bs[c * 4 + 3][row] = bv.w;
        }
        __syncthreads();
        #pragma unroll
        for (int kk = 0; kk < 32; kk++) {
            uint4 a0 = *(const uint4*)&As[kk][tr * 8];
            uint4 a1 = *(const uint4*)&As[kk][tr * 8 + 4];
            uint4 b0 = *(const uint4*)&Bs[kk][tc * 8];
            uint4 b1 = *(const uint4*)&Bs[kk][tc * 8 + 4];
            int a[8] = {(int)a0.x, (int)a0.y, (int)a0.z, (int)a0.w,
                        (int)a1.x, (int)a1.y, (int)a1.z, (int)a1.w};
            int b[8] = {(int)b0.x, (int)b0.y, (int)b0.z, (int)b0.w,
                        (int)b1.x, (int)b1.y, (int)b1.z, (int)b1.w};
            #pragma unroll
            for (int i = 0; i < 8; i++)
                #pragma unroll
                for (int j = 0; j < 8; j++)
                    iacc[i][j] = __dp4a(a[i], b[j], iacc[i][j]);
        }
        __syncthreads();
        #pragma unroll
        for (int j = 0; j < 8; j++) {
            float wv = wss[g][tc * 8 + j];
            #pragma unroll
            for (int i = 0; i < 8; i++) {
                facc[i][j] += wv * (float)iacc[i][j];
                iacc[i][j] = 0;
            }
        }
    }

    #pragma unroll
    for (int i = 0; i < 8; i++) {
        float sc = sx[rowBlk + tr * 8 + i];
        float* crow = C + (size_t)(rowBlk + tr * 8 + i) * DIM + colBlk + tc * 8;
        *(float4*)&crow[0] = make_float4(facc[i][0] * sc, facc[i][1] * sc,
                                         facc[i][2] * sc, facc[i][3] * sc);
        *(float4*)&crow[4] = make_float4(facc[i][4] * sc, facc[i][5] * sc,
                                         facc[i][6] * sc, facc[i][7] * sc);
    }
}

// ---------------- RoPE on q and k (in place) -------------------------------------
__global__ void rope_kernel(float* __restrict__ q, float* __restrict__ k,
                            const float* __restrict__ cs, const float* __restrict__ sn) {
    int idx = blockIdx.x * blockDim.x + threadIdx.x;      // B*T*NH*32 pairs
    if (idx >= 2 * TSEQ * NH * 32) return;
    int d2 = idx & 31;
    int h  = (idx >> 5) & 15;
    int tt = (idx >> 9) & (TSEQ - 1);
    int b  = idx >> 20;
    float c = cs[tt * 32 + d2], s = sn[tt * 32 + d2];
    size_t off = ((size_t)(b * TSEQ + tt)) * DIM + h * HD + d2 * 2;
    {
        float e = q[off], o = q[off + 1];
        q[off] = e * c - o * s; q[off + 1] = e * s + o * c;
    }
    {
        float e = k[off], o = k[off + 1];
        k[off] = e * c - o * s; k[off + 1] = e * s + o * c;
    }
}

// ---------------- flash attention (causal, fp32) ---------------------------------
#define QT 128
#define KT 64
#define SMEM_ATTN ((KT*HD + KT*HD + QT*66) * 4)
__global__ __launch_bounds__(QT)
void attn_kernel(const float* __restrict__ qb, const float* __restrict__ kb,
                 const float* __restrict__ vb, float* __restrict__ ob) {
    extern __shared__ float smem[];
    float* Ks = smem;                 // KT x 64
    float* Vs = Ks + KT * HD;         // KT x 64
    float* Ss = Vs + KT * HD;         // QT x 66 (padded)
    int qtile = blockIdx.x;
    int bh = blockIdx.y;
    int b = bh >> 4, h = bh & 15;
    int tid = threadIdx.x;
    int qi = qtile * QT + tid;

    const float* qrow = qb + ((size_t)(b * TSEQ + qi)) * DIM + h * HD;
    float qreg[HD];
    #pragma unroll
    for (int d = 0; d < HD; d++) qreg[d] = qrow[d];
    float acc[HD];
    #pragma unroll
    for (int d = 0; d < HD; d++) acc[d] = 0.f;
    float m = -1e30f, l = 0.f;
    float* srow = Ss + tid * 66;

    int ntiles = qtile * 2 + 2;
    for (int kt = 0; kt < ntiles; kt++) {
        int jb = kt * KT;
        for (int i = tid; i < KT * HD; i += QT) {
            int r = i >> 6, c2 = i & 63;
            size_t g = ((size_t)(b * TSEQ + jb + r)) * DIM + h * HD + c2;
            Ks[i] = kb[g];
            Vs[i] = vb[g];
        }
        __syncthreads();

        float tmax = -1e30f;
        for (int j = 0; j < KT; j++) {
            const float4* kr4 = (const float4*)(Ks + j * HD);
            float s0 = 0, s1 = 0, s2 = 0, s3 = 0;
            #pragma unroll
            for (int d4 = 0; d4 < 16; d4++) {
                float4 kv = kr4[d4];
                s0 += qreg[4 * d4 + 0] * kv.x;
                s1 += qreg[4 * d4 + 1] * kv.y;
                s2 += qreg[4 * d4 + 2] * kv.z;
                s3 += qreg[4 * d4 + 3] * kv.w;
            }
            float s = ((s0 + s1) + (s2 + s3)) * 0.125f;
            if (jb + j > qi) s = -1e30f;
            srow[j] = s;
            tmax = fmaxf(tmax, s);
        }
        float mnew = fmaxf(m, tmax);
        float corr = __expf(m - mnew);
        m = mnew;
        float sum = 0.f;
        for (int j = 0; j < KT; j++) {
            float p = __expf(srow[j] - m);
            srow[j] = p;
            sum += p;
        }
        l = l * corr + sum;
        #pragma unroll
        for (int d = 0; d < HD; d++) acc[d] *= corr;
        for (int j = 0; j < KT; j++) {
            float p = srow[j];
            const float4* vr4 = (const float4*)(Vs + j * HD);
            #pragma unroll
            for (int d4 = 0; d4 < 16; d4++) {
                float4 vv = vr4[d4];
                acc[4 * d4 + 0] += p * vv.x;
                acc[4 * d4 + 1] += p * vv.y;
                acc[4 * d4 + 2] += p * vv.z;
                acc[4 * d4 + 3] += p * vv.w;
            }
        }
        __syncthreads();
    }
    float invl = 1.f / l;
    float* orow = ob + ((size_t)(b * TSEQ + qi)) * DIM + h * HD;
    #pragma unroll
    for (int d4 = 0; d4 < 16; d4++) {
        *(float4*)&orow[4 * d4] = make_float4(acc[4 * d4 + 0] * invl, acc[4 * d4 + 1] * invl,
                                              acc[4 * d4 + 2] * invl, acc[4 * d4 + 3] * invl);
    }
}

// ---------------- launch ----------------------------------------------------------
extern "C" void kernel_launch(void* const* d_in, const int* in_sizes, int n_in,
                              void* d_out, int out_size) {
    const float* x    = (const float*)d_in[0];
    const float* cosp = (const float*)d_in[1];
    const float* sinp = (const float*)d_in[2];
    const float* wq_w = (const float*)d_in[3];
    const float* wk_w = (const float*)d_in[4];
    const float* wv_w = (const float*)d_in[5];
    const float* wo_w = (const float*)d_in[6];
    float* out = (float*)d_out;

    void* p;
    cudaGetSymbolAddress(&p, g_wi); int8_t* wip = (int8_t*)p;
    cudaGetSymbolAddress(&p, g_ws); float*  wsp = (float*)p;
    cudaGetSymbolAddress(&p, g_xi); int8_t* xip = (int8_t*)p;
    cudaGetSymbolAddress(&p, g_sx); float*  sxp = (float*)p;
    cudaGetSymbolAddress(&p, g_q);  float*  qp  = (float*)p;
    cudaGetSymbolAddress(&p, g_k);  float*  kp  = (float*)p;
    cudaGetSymbolAddress(&p, g_v);  float*  vp  = (float*)p;
    cudaGetSymbolAddress(&p, g_ao); float*  aop = (float*)p;

    cudaFuncSetAttribute(attn_kernel, cudaFuncAttributeMaxDynamicSharedMemorySize, SMEM_ATTN);

    quant_w_kernel<<<4 * DIM * 8, 128>>>(wq_w, wk_w, wv_w, wo_w);
    quant_x_kernel<<<BT, 256>>>(x, xip, sxp);

    dim3 ggrid(DIM / 128, BT / 128);
    gemm_i8_kernel<<<ggrid, 256>>>(xip, wip + 0 * DIM * DIM, wsp + 0 * DIM * 8, sxp, qp);
    gemm_i8_kernel<<<ggrid, 256>>>(xip, wip + 1 * DIM * DIM, wsp + 1 * DIM * 8, sxp, kp);
    gemm_i8_kernel<<<ggrid, 256>>>(xip, wip + 2 * DIM * DIM, wsp + 2 * DIM * 8, sxp, vp);

    int npairs = 2 * TSEQ * NH * 32;
    rope_kernel<<<(npairs + 255) / 256, 256>>>(qp, kp, cosp, sinp);

    attn_kernel<<<dim3(TSEQ / QT, 2 * NH), QT, SMEM_ATTN>>>(qp, kp, vp, aop);

    quant_x_kernel<<<BT, 256>>>(aop, xip, sxp);
    gemm_i8_kernel<<<ggrid, 256>>>(xip, wip + 3 * DIM * DIM, wsp + 3 * DIM * 8, sxp, out);
}

// round 4
// speedup vs baseline: 2.2834x; 1.5806x over previous
#include <cuda_runtime.h>
#include <cuda_bf16.h>
#include <cstdint>

#define DIM 1024
#define NH 16
#define HD 64
#define BT 4096            // B*T tokens
#define TSEQ 2048
#define GROUP 128

// ---------------- scratch (device globals; no allocation allowed) ----------------
__device__ int8_t g_wi[4 * DIM * DIM];   // ternary weights as int8: q,k,v,o
__device__ float  g_ws[4 * DIM * 8];     // per-(matrix,row,group) scales
__device__ int8_t g_xi[BT * DIM];        // int8 activations (reused)
__device__ float  g_sx[BT];              // per-token 1/s (dequant scale)
__device__ float  g_q [BT * DIM];
__device__ float  g_k [BT * DIM];
__device__ float  g_v [BT * DIM];
__device__ float  g_ao[BT * DIM];        // attention output

// ---------------- weight quantization: per-(row,group) ternary -> int8 -----------
__global__ void quant_w_kernel(const float* __restrict__ w0, const float* __restrict__ w1,
                               const float* __restrict__ w2, const float* __restrict__ w3) {
    int blk = blockIdx.x;
    int g   = blk & 7;
    int row = (blk >> 3) & (DIM - 1);
    int m   = blk >> 13;
    const float* w = (m == 0) ? w0 : (m == 1) ? w1 : (m == 2) ? w2 : w3;
    int base = row * DIM + g * GROUP;
    float v = w[base + threadIdx.x];
    float a = fabsf(v);
    #pragma unroll
    for (int o = 16; o; o >>= 1) a += __shfl_xor_sync(0xffffffffu, a, o);
    __shared__ float sh[4];
    if ((threadIdx.x & 31) == 0) sh[threadIdx.x >> 5] = a;
    __syncthreads();
    float ws = (sh[0] + sh[1] + sh[2] + sh[3]) * (1.0f / GROUP) + 1e-5f;
    float q = fminf(fmaxf(rintf(v / ws), -1.f), 1.f);
    g_wi[m * (DIM * DIM) + base + threadIdx.x] = (int8_t)q;
    if (threadIdx.x == 0) g_ws[(m * DIM + row) * 8 + g] = ws;
}

// ---------------- activation quantization: per-token absmax -> int8 --------------
__global__ void quant_x_kernel(const float* __restrict__ x, int8_t* __restrict__ xi,
                               float* __restrict__ sx) {
    int tkn = blockIdx.x;
    const float* xr = x + (size_t)tkn * DIM;
    float mx = 0.f;
    for (int i = threadIdx.x; i < DIM; i += 256) mx = fmaxf(mx, fabsf(xr[i]));
    #pragma unroll
    for (int o = 16; o; o >>= 1) mx = fmaxf(mx, __shfl_xor_sync(0xffffffffu, mx, o));
    __shared__ float sh[8];
    if ((threadIdx.x & 31) == 0) sh[threadIdx.x >> 5] = mx;
    __syncthreads();
    float m = sh[0];
    #pragma unroll
    for (int i = 1; i < 8; i++) m = fmaxf(m, sh[i]);
    float s = 127.f / (m + 1e-5f);
    for (int i = threadIdx.x; i < DIM; i += 256) {
        float v = xr[i];
        xi[(size_t)tkn * DIM + i] = (int8_t)fminf(fmaxf(rintf(v * s), -128.f), 127.f);
    }
    if (threadIdx.x == 0) sx[tkn] = 1.0f / s;
}

// ---------------- int8 dp4a GEMM with per-group scaling ---------------------------
__global__ __launch_bounds__(256, 1)
void gemm_i8_kernel(const int8_t* __restrict__ Xi, const int8_t* __restrict__ Wi,
                    const float* __restrict__ ws, const float* __restrict__ sx,
                    float* __restrict__ C) {
    __shared__ uint32_t As[32][128];
    __shared__ uint32_t Bs[32][128];
    __shared__ float    wss[8][128];
    int t = threadIdx.x;
    int rowBlk = blockIdx.y * 128;
    int colBlk = blockIdx.x * 128;
    int tr = t >> 4, tc = t & 15;

    for (int i = t; i < 8 * 128; i += 256) {
        int col = i & 127, g = i >> 7;
        wss[g][col] = ws[(colBlk + col) * 8 + g];
    }

    float facc[8][8];
    int   iacc[8][8];
    #pragma unroll
    for (int i = 0; i < 8; i++)
        #pragma unroll
        for (int j = 0; j < 8; j++) { facc[i][j] = 0.f; iacc[i][j] = 0; }

    for (int g = 0; g < 8; g++) {
        int k0 = g * GROUP;
        #pragma unroll
        for (int r = 0; r < 4; r++) {
            int u = t + 256 * r;
            int row = u >> 3, c = u & 7;
            uint4 av = *(const uint4*)(Xi + (size_t)(rowBlk + row) * DIM + k0 + c * 16);
            uint4 bv = *(const uint4*)(Wi + (size_t)(colBlk + row) * DIM + k0 + c * 16);
            As[c * 4 + 0][row] = av.x; As[c * 4 + 1][row] = av.y;
            As[c * 4 + 2][row] = av.z; As[c * 4 + 3][row] = av.w;
            Bs[c * 4 + 0][row] = bv.x; Bs[c * 4 + 1][row] = bv.y;
            Bs[c * 4 + 2][row] = bv.z; Bs[c * 4 + 3][row] = bv.w;
        }
        __syncthreads();
        #pragma unroll
        for (int kk = 0; kk < 32; kk++) {
            uint4 a0 = *(const uint4*)&As[kk][tr * 8];
            uint4 a1 = *(const uint4*)&As[kk][tr * 8 + 4];
            uint4 b0 = *(const uint4*)&Bs[kk][tc * 8];
            uint4 b1 = *(const uint4*)&Bs[kk][tc * 8 + 4];
            int a[8] = {(int)a0.x, (int)a0.y, (int)a0.z, (int)a0.w,
                        (int)a1.x, (int)a1.y, (int)a1.z, (int)a1.w};
            int b[8] = {(int)b0.x, (int)b0.y, (int)b0.z, (int)b0.w,
                        (int)b1.x, (int)b1.y, (int)b1.z, (int)b1.w};
            #pragma unroll
            for (int i = 0; i < 8; i++)
                #pragma unroll
                for (int j = 0; j < 8; j++)
                    iacc[i][j] = __dp4a(a[i], b[j], iacc[i][j]);
        }
        __syncthreads();
        #pragma unroll
        for (int j = 0; j < 8; j++) {
            float wv = wss[g][tc * 8 + j];
            #pragma unroll
            for (int i = 0; i < 8; i++) {
                facc[i][j] += wv * (float)iacc[i][j];
                iacc[i][j] = 0;
            }
        }
    }

    #pragma unroll
    for (int i = 0; i < 8; i++) {
        float sc = sx[rowBlk + tr * 8 + i];
        float* crow = C + (size_t)(rowBlk + tr * 8 + i) * DIM + colBlk + tc * 8;
        *(float4*)&crow[0] = make_float4(facc[i][0] * sc, facc[i][1] * sc,
                                         facc[i][2] * sc, facc[i][3] * sc);
        *(float4*)&crow[4] = make_float4(facc[i][4] * sc, facc[i][5] * sc,
                                         facc[i][6] * sc, facc[i][7] * sc);
    }
}

// ---------------- RoPE on q and k (in place) -------------------------------------
__global__ void rope_kernel(float* __restrict__ q, float* __restrict__ k,
                            const float* __restrict__ cs, const float* __restrict__ sn) {
    int idx = blockIdx.x * blockDim.x + threadIdx.x;
    if (idx >= 2 * TSEQ * NH * 32) return;
    int d2 = idx & 31;
    int h  = (idx >> 5) & 15;
    int tt = (idx >> 9) & (TSEQ - 1);
    int b  = idx >> 20;
    float c = cs[tt * 32 + d2], s = sn[tt * 32 + d2];
    size_t off = ((size_t)(b * TSEQ + tt)) * DIM + h * HD + d2 * 2;
    {
        float e = q[off], o = q[off + 1];
        q[off] = e * c - o * s; q[off + 1] = e * s + o * c;
    }
    {
        float e = k[off], o = k[off + 1];
        k[off] = e * c - o * s; k[off + 1] = e * s + o * c;
    }
}

// ---------- split-tf32 (3xTF32) tensor-core flash attention (causal) --------------
__device__ __forceinline__ uint32_t f2tf32(float f) {
    uint32_t r; asm("cvt.rna.tf32.f32 %0, %1;" : "=r"(r) : "f"(f)); return r;
}
__device__ __forceinline__ void split_tf32(float f, uint32_t& hi, uint32_t& lo) {
    hi = f2tf32(f);
    lo = f2tf32(f - __uint_as_float(hi));
}
__device__ __forceinline__ void mma_tf32(float* d, const uint32_t* a,
                                         const uint32_t* b, const float* c) {
    asm volatile("mma.sync.aligned.m16n8k8.row.col.f32.tf32.tf32.f32 "
        "{%0,%1,%2,%3}, {%4,%5,%6,%7}, {%8,%9}, {%10,%11,%12,%13};\n"
        : "=f"(d[0]), "=f"(d[1]), "=f"(d[2]), "=f"(d[3])
        : "r"(a[0]), "r"(a[1]), "r"(a[2]), "r"(a[3]),
          "r"(b[0]), "r"(b[1]),
          "f"(c[0]), "f"(c[1]), "f"(c[2]), "f"(c[3]));
}

#define KPAD 68
#define VPAD 72
#define SMEM_ATTN ((2*64*KPAD + 2*64*VPAD + 2*4*16*KPAD) * 4)

__global__ __launch_bounds__(128, 1)
void attn_mma_kernel(const float* __restrict__ qb, const float* __restrict__ kb,
                     const float* __restrict__ vb, float* __restrict__ ob) {
    extern __shared__ uint32_t sm[];
    uint32_t* Ksh = sm;                       // [64][KPAD] tf32 hi of K
    uint32_t* Ksl = Ksh + 64 * KPAD;          // lo
    uint32_t* Vsh = Ksl + 64 * KPAD;          // [64][VPAD] tf32 hi of V
    uint32_t* Vsl = Vsh + 64 * VPAD;          // lo
    uint32_t* Psh = Vsl + 64 * VPAD;          // [4][16][KPAD] hi of P
    uint32_t* Psl = Psh + 4 * 16 * KPAD;      // lo

    int qtile = blockIdx.x;
    int bh = blockIdx.y;
    int b = bh >> 4, h = bh & 15;
    int tid = threadIdx.x, w = tid >> 5, lane = tid & 31;
    int r0 = lane >> 2, c0 = lane & 3;
    int qrow0 = qtile * 64 + w * 16;
    uint32_t* Pwh = Psh + w * 16 * KPAD;
    uint32_t* Pwl = Psl + w * 16 * KPAD;

    // load Q fragments, pre-scaled by 1/8, split into hi/lo tf32
    uint32_t qh[8][4], ql[8][4];
    const float* qbase = qb + ((size_t)(b * TSEQ + qrow0)) * DIM + h * HD;
    #pragma unroll
    for (int s = 0; s < 8; s++) {
        split_tf32(0.125f * qbase[(size_t)r0 * DIM + s * 8 + c0],          qh[s][0], ql[s][0]);
        split_tf32(0.125f * qbase[(size_t)(r0 + 8) * DIM + s * 8 + c0],    qh[s][1], ql[s][1]);
        split_tf32(0.125f * qbase[(size_t)r0 * DIM + s * 8 + c0 + 4],      qh[s][2], ql[s][2]);
        split_tf32(0.125f * qbase[(size_t)(r0 + 8) * DIM + s * 8 + c0 + 4], qh[s][3], ql[s][3]);
    }

    float o[8][4];
    #pragma unroll
    for (int d = 0; d < 8; d++)
        #pragma unroll
        for (int j = 0; j < 4; j++) o[d][j] = 0.f;
    float mA = -1e30f, mB = -1e30f, lA = 0.f, lB = 0.f;

    int ntiles = qtile + 1;
    for (int kt = 0; kt < ntiles; kt++) {
        int jb = kt * 64;
        // cooperative load of K/V tile, split into hi/lo tf32
        for (int i = tid; i < 64 * 16; i += 128) {
            int row = i >> 4, c4 = i & 15;
            size_t gaddr = ((size_t)(b * TSEQ + jb + row)) * DIM + h * HD + c4 * 4;
            float4 kv = *(const float4*)(kb + gaddr);
            float4 vv = *(const float4*)(vb + gaddr);
            uint4 kqh, kql, vqh, vql;
            split_tf32(kv.x, kqh.x, kql.x); split_tf32(kv.y, kqh.y, kql.y);
            split_tf32(kv.z, kqh.z, kql.z); split_tf32(kv.w, kqh.w, kql.w);
            split_tf32(vv.x, vqh.x, vql.x); split_tf32(vv.y, vqh.y, vql.y);
            split_tf32(vv.z, vqh.z, vql.z); split_tf32(vv.w, vqh.w, vql.w);
            *(uint4*)&Ksh[row * KPAD + c4 * 4] = kqh;
            *(uint4*)&Ksl[row * KPAD + c4 * 4] = kql;
            *(uint4*)&Vsh[row * VPAD + c4 * 4] = vqh;
            *(uint4*)&Vsl[row * VPAD + c4 * 4] = vql;
        }
        __syncthreads();

        // S = Q K^T via 3xTF32: qh*kh + qh*kl + ql*kh
        float sc[8][4];
        #pragma unroll
        for (int ch = 0; ch < 8; ch++) {
            sc[ch][0] = sc[ch][1] = sc[ch][2] = sc[ch][3] = 0.f;
            #pragma unroll
            for (int s = 0; s < 8; s++) {
                int kidx = (ch * 8 + r0) * KPAD + s * 8 + c0;
                uint32_t bh_[2], bl_[2];
                bh_[0] = Ksh[kidx];     bh_[1] = Ksh[kidx + 4];
                bl_[0] = Ksl[kidx];     bl_[1] = Ksl[kidx + 4];
                mma_tf32(sc[ch], qh[s], bl_, sc[ch]);
                mma_tf32(sc[ch], ql[s], bh_, sc[ch]);
                mma_tf32(sc[ch], qh[s], bh_, sc[ch]);
            }
        }

        // causal mask on diagonal tile
        if (kt == ntiles - 1) {
            int qiA = qrow0 + r0, qiB = qrow0 + r0 + 8;
            #pragma unroll
            for (int ch = 0; ch < 8; ch++) {
                int j0 = jb + ch * 8 + 2 * c0;
                if (j0     > qiA) sc[ch][0] = -1e30f;
                if (j0 + 1 > qiA) sc[ch][1] = -1e30f;
                if (j0     > qiB) sc[ch][2] = -1e30f;
                if (j0 + 1 > qiB) sc[ch][3] = -1e30f;
            }
        }

        // row max across quad
        float tA = -1e30f, tB = -1e30f;
        #pragma unroll
        for (int ch = 0; ch < 8; ch++) {
            tA = fmaxf(tA, fmaxf(sc[ch][0], sc[ch][1]));
            tB = fmaxf(tB, fmaxf(sc[ch][2], sc[ch][3]));
        }
        tA = fmaxf(tA, __shfl_xor_sync(0xffffffffu, tA, 1));
        tA = fmaxf(tA, __shfl_xor_sync(0xffffffffu, tA, 2));
        tB = fmaxf(tB, __shfl_xor_sync(0xffffffffu, tB, 1));
        tB = fmaxf(tB, __shfl_xor_sync(0xffffffffu, tB, 2));

        float mAn = fmaxf(mA, tA), mBn = fmaxf(mB, tB);
        float corrA = __expf(mA - mAn), corrB = __expf(mB - mBn);
        mA = mAn; mB = mBn;

        float sumA = 0.f, sumB = 0.f;
        #pragma unroll
        for (int ch = 0; ch < 8; ch++) {
            float p0 = __expf(sc[ch][0] - mA);
            float p1 = __expf(sc[ch][1] - mA);
            float p2 = __expf(sc[ch][2] - mB);
            float p3 = __expf(sc[ch][3] - mB);
            sumA += p0 + p1; sumB += p2 + p3;
            uint32_t h0, l0, h1, l1;
            split_tf32(p0, h0, l0); split_tf32(p1, h1, l1);
            *(uint2*)&Pwh[r0 * KPAD + ch * 8 + 2 * c0] = make_uint2(h0, h1);
            *(uint2*)&Pwl[r0 * KPAD + ch * 8 + 2 * c0] = make_uint2(l0, l1);
            split_tf32(p2, h0, l0); split_tf32(p3, h1, l1);
            *(uint2*)&Pwh[(r0 + 8) * KPAD + ch * 8 + 2 * c0] = make_uint2(h0, h1);
            *(uint2*)&Pwl[(r0 + 8) * KPAD + ch * 8 + 2 * c0] = make_uint2(l0, l1);
        }
        sumA += __shfl_xor_sync(0xffffffffu, sumA, 1);
        sumA += __shfl_xor_sync(0xffffffffu, sumA, 2);
        sumB += __shfl_xor_sync(0xffffffffu, sumB, 1);
        sumB += __shfl_xor_sync(0xffffffffu, sumB, 2);
        lA = lA * corrA + sumA;
        lB = lB * corrB + sumB;
        #pragma unroll
        for (int d = 0; d < 8; d++) {
            o[d][0] *= corrA; o[d][1] *= corrA;
            o[d][2] *= corrB; o[d][3] *= corrB;
        }
        __syncwarp();

        // O += P V via 3xTF32: ph*vh + ph*vl + pl*vh
        #pragma unroll
        for (int s = 0; s < 8; s++) {
            uint32_t ah_[4], al_[4];
            ah_[0] = Pwh[r0 * KPAD + s * 8 + c0];
            ah_[1] = Pwh[(r0 + 8) * KPAD + s * 8 + c0];
            ah_[2] = Pwh[r0 * KPAD + s * 8 + c0 + 4];
            ah_[3] = Pwh[(r0 + 8) * KPAD + s * 8 + c0 + 4];
            al_[0] = Pwl[r0 * KPAD + s * 8 + c0];
            al_[1] = Pwl[(r0 + 8) * KPAD + s * 8 + c0];
            al_[2] = Pwl[r0 * KPAD + s * 8 + c0 + 4];
            al_[3] = Pwl[(r0 + 8) * KPAD + s * 8 + c0 + 4];
            #pragma unroll
            for (int d = 0; d < 8; d++) {
                int v0 = (s * 8 + c0) * VPAD + d * 8 + r0;
                int v1 = (s * 8 + c0 + 4) * VPAD + d * 8 + r0;
                uint32_t bh_[2], bl_[2];
                bh_[0] = Vsh[v0]; bh_[1] = Vsh[v1];
                bl_[0] = Vsl[v0]; bl_[1] = Vsl[v1];
                mma_tf32(o[d], ah_, bl_, o[d]);
                mma_tf32(o[d], al_, bh_, o[d]);
                mma_tf32(o[d], ah_, bh_, o[d]);
            }
        }
        __syncthreads();
    }

    float invA = 1.f / lA, invB = 1.f / lB;
    float* obase = ob + ((size_t)(b * TSEQ + qrow0)) * DIM + h * HD;
    #pragma unroll
    for (int d = 0; d < 8; d++) {
        *(float2*)&obase[(size_t)r0 * DIM + d * 8 + 2 * c0] =
            make_float2(o[d][0] * invA, o[d][1] * invA);
        *(float2*)&obase[(size_t)(r0 + 8) * DIM + d * 8 + 2 * c0] =
            make_float2(o[d][2] * invB, o[d][3] * invB);
    }
}

// ---------------- launch ----------------------------------------------------------
extern "C" void kernel_launch(void* const* d_in, const int* in_sizes, int n_in,
                              void* d_out, int out_size) {
    const float* x    = (const float*)d_in[0];
    const float* cosp = (const float*)d_in[1];
    const float* sinp = (const float*)d_in[2];
    const float* wq_w = (const float*)d_in[3];
    const float* wk_w = (const float*)d_in[4];
    const float* wv_w = (const float*)d_in[5];
    const float* wo_w = (const float*)d_in[6];
    float* out = (float*)d_out;

    void* p;
    cudaGetSymbolAddress(&p, g_wi); int8_t* wip = (int8_t*)p;
    cudaGetSymbolAddress(&p, g_ws); float*  wsp = (float*)p;
    cudaGetSymbolAddress(&p, g_xi); int8_t* xip = (int8_t*)p;
    cudaGetSymbolAddress(&p, g_sx); float*  sxp = (float*)p;
    cudaGetSymbolAddress(&p, g_q);  float*  qp  = (float*)p;
    cudaGetSymbolAddress(&p, g_k);  float*  kp  = (float*)p;
    cudaGetSymbolAddress(&p, g_v);  float*  vp  = (float*)p;
    cudaGetSymbolAddress(&p, g_ao); float*  aop = (float*)p;

    cudaFuncSetAttribute(attn_mma_kernel, cudaFuncAttributeMaxDynamicSharedMemorySize, SMEM_ATTN);

    quant_w_kernel<<<4 * DIM * 8, 128>>>(wq_w, wk_w, wv_w, wo_w);
    quant_x_kernel<<<BT, 256>>>(x, xip, sxp);

    dim3 ggrid(DIM / 128, BT / 128);
    gemm_i8_kernel<<<ggrid, 256>>>(xip, wip + 0 * DIM * DIM, wsp + 0 * DIM * 8, sxp, qp);
    gemm_i8_kernel<<<ggrid, 256>>>(xip, wip + 1 * DIM * DIM, wsp + 1 * DIM * 8, sxp, kp);
    gemm_i8_kernel<<<ggrid, 256>>>(xip, wip + 2 * DIM * DIM, wsp + 2 * DIM * 8, sxp, vp);

    int npairs = 2 * TSEQ * NH * 32;
    rope_kernel<<<(npairs + 255) / 256, 256>>>(qp, kp, cosp, sinp);

    attn_mma_kernel<<<dim3(TSEQ / 64, 2 * NH), 128, SMEM_ATTN>>>(qp, kp, vp, aop);

    quant_x_kernel<<<BT, 256>>>(aop, xip, sxp);
    gemm_i8_kernel<<<ggrid, 256>>>(xip, wip + 3 * DIM * DIM, wsp + 3 * DIM * 8, sxp, out);
}

// round 5
// speedup vs baseline: 2.4635x; 1.0789x over previous
#include <cuda_runtime.h>
#include <cuda_bf16.h>
#include <cstdint>

#define DIM 1024
#define NH 16
#define HD 64
#define BT 4096            // B*T tokens
#define TSEQ 2048
#define GROUP 128

// ---------------- scratch (device globals; no allocation allowed) ----------------
__device__ int8_t g_wi[4 * DIM * DIM];   // ternary weights as int8: q,k,v,o
__device__ float  g_ws[4 * DIM * 8];     // per-(matrix,row,group) scales
__device__ int8_t g_xi[BT * DIM];        // int8 activations (reused)
__device__ float  g_sx[BT];              // per-token 1/s (dequant scale)
__device__ float  g_q [BT * DIM];
__device__ float  g_k [BT * DIM];
__device__ float  g_v [BT * DIM];
__device__ float  g_ao[BT * DIM];        // attention output

// ---------------- weight quantization: per-(row,group) ternary -> int8 -----------
__global__ void quant_w_kernel(const float* __restrict__ w0, const float* __restrict__ w1,
                               const float* __restrict__ w2, const float* __restrict__ w3) {
    int blk = blockIdx.x;
    int g   = blk & 7;
    int row = (blk >> 3) & (DIM - 1);
    int m   = blk >> 13;
    const float* w = (m == 0) ? w0 : (m == 1) ? w1 : (m == 2) ? w2 : w3;
    int base = row * DIM + g * GROUP;
    float v = w[base + threadIdx.x];
    float a = fabsf(v);
    #pragma unroll
    for (int o = 16; o; o >>= 1) a += __shfl_xor_sync(0xffffffffu, a, o);
    __shared__ float sh[4];
    if ((threadIdx.x & 31) == 0) sh[threadIdx.x >> 5] = a;
    __syncthreads();
    float ws = (sh[0] + sh[1] + sh[2] + sh[3]) * (1.0f / GROUP) + 1e-5f;
    float q = fminf(fmaxf(rintf(v / ws), -1.f), 1.f);
    g_wi[m * (DIM * DIM) + base + threadIdx.x] = (int8_t)q;
    if (threadIdx.x == 0) g_ws[(m * DIM + row) * 8 + g] = ws;
}

// ---------------- activation quantization: per-token absmax -> int8 --------------
__global__ void quant_x_kernel(const float* __restrict__ x, int8_t* __restrict__ xi,
                               float* __restrict__ sx) {
    int tkn = blockIdx.x;
    const float* xr = x + (size_t)tkn * DIM;
    float mx = 0.f;
    for (int i = threadIdx.x; i < DIM; i += 256) mx = fmaxf(mx, fabsf(xr[i]));
    #pragma unroll
    for (int o = 16; o; o >>= 1) mx = fmaxf(mx, __shfl_xor_sync(0xffffffffu, mx, o));
    __shared__ float sh[8];
    if ((threadIdx.x & 31) == 0) sh[threadIdx.x >> 5] = mx;
    __syncthreads();
    float m = sh[0];
    #pragma unroll
    for (int i = 1; i < 8; i++) m = fmaxf(m, sh[i]);
    float s = 127.f / (m + 1e-5f);
    for (int i = threadIdx.x; i < DIM; i += 256) {
        float v = xr[i];
        xi[(size_t)tkn * DIM + i] = (int8_t)fminf(fmaxf(rintf(v * s), -128.f), 127.f);
    }
    if (threadIdx.x == 0) sx[tkn] = 1.0f / s;
}

// ---------------- int8 tensor-core GEMM with per-group scaling --------------------
// C[t,o] = sx[t] * sum_g ws[o,g] * (int32 dot over group g of xi[t]*wi[o])
// block tile 128x128, 8 warps (2m x 4n), warp tile 64x32, mma m16n8k32
__device__ __forceinline__ void mma_s8(int* d, const int* a, const int* b) {
    asm volatile("mma.sync.aligned.m16n8k32.row.col.s32.s8.s8.s32 "
        "{%0,%1,%2,%3}, {%4,%5,%6,%7}, {%8,%9}, {%0,%1,%2,%3};\n"
        : "+r"(d[0]), "+r"(d[1]), "+r"(d[2]), "+r"(d[3])
        : "r"(a[0]), "r"(a[1]), "r"(a[2]), "r"(a[3]), "r"(b[0]), "r"(b[1]));
}

#define GPAD 144
__global__ __launch_bounds__(256, 1)
void gemm_i8mma_kernel(const int8_t* __restrict__ Xi, const int8_t* __restrict__ Wi,
                       const float* __restrict__ ws, const float* __restrict__ sx,
                       float* __restrict__ C) {
    __shared__ int8_t As[128 * GPAD];
    __shared__ int8_t Bs[128 * GPAD];
    __shared__ float  wss[8][128];
    int t = threadIdx.x;
    int rowBlk = blockIdx.y * 128;
    int colBlk = blockIdx.x * 128;
    int warpId = t >> 5, lane = t & 31;
    int gid = lane >> 2, tig = lane & 3;
    int wm = (warpId >> 2) * 64;
    int wn = (warpId & 3) * 32;

    for (int i = t; i < 8 * 128; i += 256) {
        int col = i & 127, g = i >> 7;
        wss[g][col] = ws[(colBlk + col) * 8 + g];
    }

    int   iacc[4][4][4];
    float facc[4][4][4];
    #pragma unroll
    for (int mt = 0; mt < 4; mt++)
        #pragma unroll
        for (int nt = 0; nt < 4; nt++)
            #pragma unroll
            for (int r = 0; r < 4; r++) { iacc[mt][nt][r] = 0; facc[mt][nt][r] = 0.f; }

    for (int g = 0; g < 8; g++) {
        int k0 = g * GROUP;
        #pragma unroll
        for (int r = 0; r < 4; r++) {
            int u = t + 256 * r;               // 0..1023
            int row = u >> 3, c = u & 7;
            *(uint4*)&As[row * GPAD + c * 16] =
                *(const uint4*)(Xi + (size_t)(rowBlk + row) * DIM + k0 + c * 16);
            *(uint4*)&Bs[row * GPAD + c * 16] =
                *(const uint4*)(Wi + (size_t)(colBlk + row) * DIM + k0 + c * 16);
        }
        __syncthreads();

        #pragma unroll
        for (int ks = 0; ks < 4; ks++) {
            int a[4][4], b[4][2];
            #pragma unroll
            for (int mt = 0; mt < 4; mt++) {
                int row = wm + mt * 16 + gid;
                a[mt][0] = *(const int*)&As[row * GPAD + ks * 32 + tig * 4];
                a[mt][1] = *(const int*)&As[(row + 8) * GPAD + ks * 32 + tig * 4];
                a[mt][2] = *(const int*)&As[row * GPAD + ks * 32 + tig * 4 + 16];
                a[mt][3] = *(const int*)&As[(row + 8) * GPAD + ks * 32 + tig * 4 + 16];
            }
            #pragma unroll
            for (int nt = 0; nt < 4; nt++) {
                int col = wn + nt * 8 + gid;
                b[nt][0] = *(const int*)&Bs[col * GPAD + ks * 32 + tig * 4];
                b[nt][1] = *(const int*)&Bs[col * GPAD + ks * 32 + tig * 4 + 16];
            }
            #pragma unroll
            for (int mt = 0; mt < 4; mt++)
                #pragma unroll
                for (int nt = 0; nt < 4; nt++)
                    mma_s8(iacc[mt][nt], a[mt], b[nt]);
        }
        __syncthreads();

        #pragma unroll
        for (int nt = 0; nt < 4; nt++) {
            float w0 = wss[g][wn + nt * 8 + 2 * tig];
            float w1 = wss[g][wn + nt * 8 + 2 * tig + 1];
            #pragma unroll
            for (int mt = 0; mt < 4; mt++) {
                facc[mt][nt][0] += w0 * (float)iacc[mt][nt][0]; iacc[mt][nt][0] = 0;
                facc[mt][nt][1] += w1 * (float)iacc[mt][nt][1]; iacc[mt][nt][1] = 0;
                facc[mt][nt][2] += w0 * (float)iacc[mt][nt][2]; iacc[mt][nt][2] = 0;
                facc[mt][nt][3] += w1 * (float)iacc[mt][nt][3]; iacc[mt][nt][3] = 0;
            }
        }
    }

    #pragma unroll
    for (int mt = 0; mt < 4; mt++) {
        int row0 = rowBlk + wm + mt * 16 + gid;
        float s0 = sx[row0], s1 = sx[row0 + 8];
        #pragma unroll
        for (int nt = 0; nt < 4; nt++) {
            int col = colBlk + wn + nt * 8 + 2 * tig;
            *(float2*)&C[(size_t)row0 * DIM + col] =
                make_float2(facc[mt][nt][0] * s0, facc[mt][nt][1] * s0);
            *(float2*)&C[(size_t)(row0 + 8) * DIM + col] =
                make_float2(facc[mt][nt][2] * s1, facc[mt][nt][3] * s1);
        }
    }
}

// ---------------- RoPE on q and k (in place) -------------------------------------
__global__ void rope_kernel(float* __restrict__ q, float* __restrict__ k,
                            const float* __restrict__ cs, const float* __restrict__ sn) {
    int idx = blockIdx.x * blockDim.x + threadIdx.x;
    if (idx >= 2 * TSEQ * NH * 32) return;
    int d2 = idx & 31;
    int h  = (idx >> 5) & 15;
    int tt = (idx >> 9) & (TSEQ - 1);
    int b  = idx >> 20;
    float c = cs[tt * 32 + d2], s = sn[tt * 32 + d2];
    size_t off = ((size_t)(b * TSEQ + tt)) * DIM + h * HD + d2 * 2;
    {
        float e = q[off], o = q[off + 1];
        q[off] = e * c - o * s; q[off + 1] = e * s + o * c;
    }
    {
        float e = k[off], o = k[off + 1];
        k[off] = e * c - o * s; k[off + 1] = e * s + o * c;
    }
}

// ---------- split-tf32 (3xTF32) tensor-core flash attention (causal) --------------
__device__ __forceinline__ uint32_t f2tf32(float f) {
    uint32_t r; asm("cvt.rna.tf32.f32 %0, %1;" : "=r"(r) : "f"(f)); return r;
}
__device__ __forceinline__ void split_tf32(float f, uint32_t& hi, uint32_t& lo) {
    hi = f2tf32(f);
    lo = f2tf32(f - __uint_as_float(hi));
}
__device__ __forceinline__ void mma_tf32(float* d, const uint32_t* a,
                                         const uint32_t* b, const float* c) {
    asm volatile("mma.sync.aligned.m16n8k8.row.col.f32.tf32.tf32.f32 "
        "{%0,%1,%2,%3}, {%4,%5,%6,%7}, {%8,%9}, {%10,%11,%12,%13};\n"
        : "=f"(d[0]), "=f"(d[1]), "=f"(d[2]), "=f"(d[3])
        : "r"(a[0]), "r"(a[1]), "r"(a[2]), "r"(a[3]),
          "r"(b[0]), "r"(b[1]),
          "f"(c[0]), "f"(c[1]), "f"(c[2]), "f"(c[3]));
}

#define KPAD 68
#define VPAD 72
#define SMEM_ATTN ((2*64*KPAD + 2*64*VPAD) * 4)

__global__ __launch_bounds__(128)
void attn_mma_kernel(const float* __restrict__ qb, const float* __restrict__ kb,
                     const float* __restrict__ vb, float* __restrict__ ob) {
    extern __shared__ uint32_t sm[];
    uint32_t* Ksh = sm;                       // [64][KPAD] tf32 hi of K
    uint32_t* Ksl = Ksh + 64 * KPAD;          // lo
    uint32_t* Vsh = Ksl + 64 * KPAD;          // [64][VPAD] tf32 hi of V
    uint32_t* Vsl = Vsh + 64 * VPAD;          // lo

    int qtile = blockIdx.x;
    int bh = blockIdx.y;
    int b = bh >> 4, h = bh & 15;
    int tid = threadIdx.x, w = tid >> 5, lane = tid & 31;
    int r0 = lane >> 2, c0 = lane & 3;
    int qrow0 = qtile * 64 + w * 16;

    // load Q fragments, pre-scaled by 1/8, split into hi/lo tf32
    uint32_t qh[8][4], ql[8][4];
    const float* qbase = qb + ((size_t)(b * TSEQ + qrow0)) * DIM + h * HD;
    #pragma unroll
    for (int s = 0; s < 8; s++) {
        split_tf32(0.125f * qbase[(size_t)r0 * DIM + s * 8 + c0],           qh[s][0], ql[s][0]);
        split_tf32(0.125f * qbase[(size_t)(r0 + 8) * DIM + s * 8 + c0],     qh[s][1], ql[s][1]);
        split_tf32(0.125f * qbase[(size_t)r0 * DIM + s * 8 + c0 + 4],       qh[s][2], ql[s][2]);
        split_tf32(0.125f * qbase[(size_t)(r0 + 8) * DIM + s * 8 + c0 + 4], qh[s][3], ql[s][3]);
    }

    float o[8][4];
    #pragma unroll
    for (int d = 0; d < 8; d++)
        #pragma unroll
        for (int j = 0; j < 4; j++) o[d][j] = 0.f;
    float mA = -1e30f, mB = -1e30f, lA = 0.f, lB = 0.f;

    int ntiles = qtile + 1;
    for (int kt = 0; kt < ntiles; kt++) {
        int jb = kt * 64;
        for (int i = tid; i < 64 * 16; i += 128) {
            int row = i >> 4, c4 = i & 15;
            size_t gaddr = ((size_t)(b * TSEQ + jb + row)) * DIM + h * HD + c4 * 4;
            float4 kv = *(const float4*)(kb + gaddr);
            float4 vv = *(const float4*)(vb + gaddr);
            uint4 kqh, kql, vqh, vql;
            split_tf32(kv.x, kqh.x, kql.x); split_tf32(kv.y, kqh.y, kql.y);
            split_tf32(kv.z, kqh.z, kql.z); split_tf32(kv.w, kqh.w, kql.w);
            split_tf32(vv.x, vqh.x, vql.x); split_tf32(vv.y, vqh.y, vql.y);
            split_tf32(vv.z, vqh.z, vql.z); split_tf32(vv.w, vqh.w, vql.w);
            *(uint4*)&Ksh[row * KPAD + c4 * 4] = kqh;
            *(uint4*)&Ksl[row * KPAD + c4 * 4] = kql;
            *(uint4*)&Vsh[row * VPAD + c4 * 4] = vqh;
            *(uint4*)&Vsl[row * VPAD + c4 * 4] = vql;
        }
        __syncthreads();

        // S = Q K^T via 3xTF32
        float sc[8][4];
        #pragma unroll
        for (int ch = 0; ch < 8; ch++) {
            sc[ch][0] = sc[ch][1] = sc[ch][2] = sc[ch][3] = 0.f;
            #pragma unroll
            for (int s = 0; s < 8; s++) {
                int kidx = (ch * 8 + r0) * KPAD + s * 8 + c0;
                uint32_t bh_[2], bl_[2];
                bh_[0] = Ksh[kidx];     bh_[1] = Ksh[kidx + 4];
                bl_[0] = Ksl[kidx];     bl_[1] = Ksl[kidx + 4];
                mma_tf32(sc[ch], qh[s], bl_, sc[ch]);
                mma_tf32(sc[ch], ql[s], bh_, sc[ch]);
                mma_tf32(sc[ch], qh[s], bh_, sc[ch]);
            }
        }

        // causal mask on diagonal tile
        if (kt == ntiles - 1) {
            int qiA = qrow0 + r0, qiB = qrow0 + r0 + 8;
            #pragma unroll
            for (int ch = 0; ch < 8; ch++) {
                int j0 = jb + ch * 8 + 2 * c0;
                if (j0     > qiA) sc[ch][0] = -1e30f;
                if (j0 + 1 > qiA) sc[ch][1] = -1e30f;
                if (j0     > qiB) sc[ch][2] = -1e30f;
                if (j0 + 1 > qiB) sc[ch][3] = -1e30f;
            }
        }

        // row max across quad
        float tA = -1e30f, tB = -1e30f;
        #pragma unroll
        for (int ch = 0; ch < 8; ch++) {
            tA = fmaxf(tA, fmaxf(sc[ch][0], sc[ch][1]));
            tB = fmaxf(tB, fmaxf(sc[ch][2], sc[ch][3]));
        }
        tA = fmaxf(tA, __shfl_xor_sync(0xffffffffu, tA, 1));
        tA = fmaxf(tA, __shfl_xor_sync(0xffffffffu, tA, 2));
        tB = fmaxf(tB, __shfl_xor_sync(0xffffffffu, tB, 1));
        tB = fmaxf(tB, __shfl_xor_sync(0xffffffffu, tB, 2));

        float mAn = fmaxf(mA, tA), mBn = fmaxf(mB, tB);
        float corrA = __expf(mA - mAn), corrB = __expf(mB - mBn);
        mA = mAn; mB = mBn;

        float sumA = 0.f, sumB = 0.f;
        #pragma unroll
        for (int ch = 0; ch < 8; ch++) {
            sc[ch][0] = __expf(sc[ch][0] - mA);
            sc[ch][1] = __expf(sc[ch][1] - mA);
            sc[ch][2] = __expf(sc[ch][2] - mB);
            sc[ch][3] = __expf(sc[ch][3] - mB);
            sumA += sc[ch][0] + sc[ch][1];
            sumB += sc[ch][2] + sc[ch][3];
        }
        sumA += __shfl_xor_sync(0xffffffffu, sumA, 1);
        sumA += __shfl_xor_sync(0xffffffffu, sumA, 2);
        sumB += __shfl_xor_sync(0xffffffffu, sumB, 1);
        sumB += __shfl_xor_sync(0xffffffffu, sumB, 2);
        lA = lA * corrA + sumA;
        lB = lB * corrB + sumB;
        #pragma unroll
        for (int d = 0; d < 8; d++) {
            o[d][0] *= corrA; o[d][1] *= corrA;
            o[d][2] *= corrB; o[d][3] *= corrB;
        }

        // O += P V via 3xTF32; P A-fragments built by register shuffle from C-layout
        int srcA = r0 * 4 + (c0 >> 1);
        bool odd = (c0 & 1);
        #pragma unroll
        for (int s = 0; s < 8; s++) {
            float v0 = __shfl_sync(0xffffffffu, sc[s][0], srcA);
            float v1 = __shfl_sync(0xffffffffu, sc[s][1], srcA);
            float v2 = __shfl_sync(0xffffffffu, sc[s][2], srcA);
            float v3 = __shfl_sync(0xffffffffu, sc[s][3], srcA);
            float w0 = __shfl_sync(0xffffffffu, sc[s][0], srcA + 2);
            float w1 = __shfl_sync(0xffffffffu, sc[s][1], srcA + 2);
            float w2 = __shfl_sync(0xffffffffu, sc[s][2], srcA + 2);
            float w3 = __shfl_sync(0xffffffffu, sc[s][3], srcA + 2);
            float aP0 = odd ? v1 : v0;     // row r0,   key s*8+c0
            float aP1 = odd ? v3 : v2;     // row r0+8, key s*8+c0
            float aP2 = odd ? w1 : w0;     // row r0,   key s*8+c0+4
            float aP3 = odd ? w3 : w2;     // row r0+8, key s*8+c0+4
            uint32_t ah_[4], al_[4];
            split_tf32(aP0, ah_[0], al_[0]);
            split_tf32(aP1, ah_[1], al_[1]);
            split_tf32(aP2, ah_[2], al_[2]);
            split_tf32(aP3, ah_[3], al_[3]);
            #pragma unroll
            for (int d = 0; d < 8; d++) {
                int v0i = (s * 8 + c0) * VPAD + d * 8 + r0;
                int v1i = (s * 8 + c0 + 4) * VPAD + d * 8 + r0;
                uint32_t bh_[2], bl_[2];
                bh_[0] = Vsh[v0i]; bh_[1] = Vsh[v1i];
                bl_[0] = Vsl[v0i]; bl_[1] = Vsl[v1i];
                mma_tf32(o[d], ah_, bl_, o[d]);
                mma_tf32(o[d], al_, bh_, o[d]);
                mma_tf32(o[d], ah_, bh_, o[d]);
            }
        }
        __syncthreads();
    }

    float invA = 1.f / lA, invB = 1.f / lB;
    float* obase = ob + ((size_t)(b * TSEQ + qrow0)) * DIM + h * HD;
    #pragma unroll
    for (int d = 0; d < 8; d++) {
        *(float2*)&obase[(size_t)r0 * DIM + d * 8 + 2 * c0] =
            make_float2(o[d][0] * invA, o[d][1] * invA);
        *(float2*)&obase[(size_t)(r0 + 8) * DIM + d * 8 + 2 * c0] =
            make_float2(o[d][2] * invB, o[d][3] * invB);
    }
}

// ---------------- launch ----------------------------------------------------------
extern "C" void kernel_launch(void* const* d_in, const int* in_sizes, int n_in,
                              void* d_out, int out_size) {
    const float* x    = (const float*)d_in[0];
    const float* cosp = (const float*)d_in[1];
    const float* sinp = (const float*)d_in[2];
    const float* wq_w = (const float*)d_in[3];
    const float* wk_w = (const float*)d_in[4];
    const float* wv_w = (const float*)d_in[5];
    const float* wo_w = (const float*)d_in[6];
    float* out = (float*)d_out;

    void* p;
    cudaGetSymbolAddress(&p, g_wi); int8_t* wip = (int8_t*)p;
    cudaGetSymbolAddress(&p, g_ws); float*  wsp = (float*)p;
    cudaGetSymbolAddress(&p, g_xi); int8_t* xip = (int8_t*)p;
    cudaGetSymbolAddress(&p, g_sx); float*  sxp = (float*)p;
    cudaGetSymbolAddress(&p, g_q);  float*  qp  = (float*)p;
    cudaGetSymbolAddress(&p, g_k);  float*  kp  = (float*)p;
    cudaGetSymbolAddress(&p, g_v);  float*  vp  = (float*)p;
    cudaGetSymbolAddress(&p, g_ao); float*  aop = (float*)p;

    cudaFuncSetAttribute(attn_mma_kernel, cudaFuncAttributeMaxDynamicSharedMemorySize, SMEM_ATTN);

    quant_w_kernel<<<4 * DIM * 8, 128>>>(wq_w, wk_w, wv_w, wo_w);
    quant_x_kernel<<<BT, 256>>>(x, xip, sxp);

    dim3 ggrid(DIM / 128, BT / 128);
    gemm_i8mma_kernel<<<ggrid, 256>>>(xip, wip + 0 * DIM * DIM, wsp + 0 * DIM * 8, sxp, qp);
    gemm_i8mma_kernel<<<ggrid, 256>>>(xip, wip + 1 * DIM * DIM, wsp + 1 * DIM * 8, sxp, kp);
    gemm_i8mma_kernel<<<ggrid, 256>>>(xip, wip + 2 * DIM * DIM, wsp + 2 * DIM * 8, sxp, vp);

    int npairs = 2 * TSEQ * NH * 32;
    rope_kernel<<<(npairs + 255) / 256, 256>>>(qp, kp, cosp, sinp);

    attn_mma_kernel<<<dim3(TSEQ / 64, 2 * NH), 128, SMEM_ATTN>>>(qp, kp, vp, aop);

    quant_x_kernel<<<BT, 256>>>(aop, xip, sxp);
    gemm_i8mma_kernel<<<ggrid, 256>>>(xip, wip + 3 * DIM * DIM, wsp + 3 * DIM * 8, sxp, out);
}